// round 2
// baseline (speedup 1.0000x reference)
#include <cuda_runtime.h>
#include <math.h>

// LSTM cell fused kernel, TF32 mma.sync path.
// M=BATCH=4096, N=HIDDEN=2048, K = 2048 (x) + 2048 (h) = 4096 effective.
// Computes all 4 gate pre-activations per output tile in one CTA, then the
// elementwise LSTM update, writing [hy ; cy] to d_out.

#define MDIM 4096
#define NDIM 2048
#define KIN  2048
#define BM 64
#define BN 64
#define BK 16
#define KT 256            // 4096 / 16
#define THREADS 256

#define AS_STRIDE 20      // 64 rows x 20 (16 + 4 pad) -> conflict-free frag loads
#define BS_STRIDE 72      // 16 rows x 72 (64 + 8 pad) -> conflict-free frag loads
#define AS_SIZE   (BM * AS_STRIDE)        // 1280 words
#define BS_SIZE   (4 * BK * BS_STRIDE)    // 4608 words
#define STAGE_SIZE (AS_SIZE + BS_SIZE)    // 5888 words
#define SMEM_WORDS (2 * STAGE_SIZE)       // 11776 words = 47104 B (< 48KB)

__device__ __forceinline__ unsigned f2tf32(float f) {
    unsigned r;
    asm("cvt.rna.tf32.f32 %0, %1;" : "=r"(r) : "f"(f));
    return r;
}

__device__ __forceinline__ void mma_tf32(float c[4],
                                         unsigned a0, unsigned a1, unsigned a2, unsigned a3,
                                         unsigned b0, unsigned b1) {
    asm volatile(
        "mma.sync.aligned.m16n8k8.row.col.f32.tf32.tf32.f32 "
        "{%0,%1,%2,%3}, {%4,%5,%6,%7}, {%8,%9}, {%0,%1,%2,%3};\n"
        : "+f"(c[0]), "+f"(c[1]), "+f"(c[2]), "+f"(c[3])
        : "r"(a0), "r"(a1), "r"(a2), "r"(a3), "r"(b0), "r"(b1));
}

__global__ __launch_bounds__(THREADS)
void lstm_fused_tf32_kernel(
    const float* __restrict__ x,   const float* __restrict__ hx,  const float* __restrict__ cx,
    const float* __restrict__ Wxi, const float* __restrict__ Whi, const float* __restrict__ bi,
    const float* __restrict__ Wxf, const float* __restrict__ Whf, const float* __restrict__ bf_,
    const float* __restrict__ Wxc, const float* __restrict__ Whc, const float* __restrict__ bc,
    const float* __restrict__ Wxo, const float* __restrict__ Who, const float* __restrict__ bo,
    float* __restrict__ out)
{
    extern __shared__ unsigned smem[];

    const int tid  = threadIdx.x;
    const int lane = tid & 31;
    const int wid  = tid >> 5;
    const int g    = wid & 3;   // gate: 0=i 1=f 2=c 3=o
    const int mh   = wid >> 2;  // m-half: 0 or 1 (rows 0-31 / 32-63 of tile)

    const int bm = blockIdx.y * BM;
    const int bn = blockIdx.x * BN;

    const float* const Wx[4] = {Wxi, Wxf, Wxc, Wxo};
    const float* const Wh[4] = {Whi, Whf, Whc, Who};

    // accumulators: [m-subtile (16 rows)][n-subtile (8 cols)][frag]
    float acc[2][8][4];
#pragma unroll
    for (int t = 0; t < 2; t++)
#pragma unroll
        for (int j = 0; j < 8; j++)
#pragma unroll
            for (int q = 0; q < 4; q++) acc[t][j][q] = 0.0f;

    // global load indexing
    const int arow = tid >> 2;          // 0..63
    const int acol = (tid & 3) * 4;     // 0,4,8,12
    const int brow = tid >> 4;          // 0..15
    const int bcol = (tid & 15) * 4;    // 0..60

    const int r = lane >> 2;            // 0..7
    const int c = lane & 3;             // 0..3

    // ---- prologue: load tile 0 into stage 0 ----
    {
        const float4 av = *(const float4*)(x + (size_t)(bm + arow) * KIN + acol);
        unsigned* As = smem;
        uint4 ua;
        ua.x = f2tf32(av.x); ua.y = f2tf32(av.y); ua.z = f2tf32(av.z); ua.w = f2tf32(av.w);
        *(uint4*)(As + arow * AS_STRIDE + acol) = ua;

        unsigned* Bs = smem + AS_SIZE;
#pragma unroll
        for (int gg = 0; gg < 4; gg++) {
            const float4 bv = *(const float4*)(Wx[gg] + (size_t)brow * NDIM + bn + bcol);
            uint4 ub;
            ub.x = f2tf32(bv.x); ub.y = f2tf32(bv.y); ub.z = f2tf32(bv.z); ub.w = f2tf32(bv.w);
            *(uint4*)(Bs + gg * BK * BS_STRIDE + brow * BS_STRIDE + bcol) = ub;
        }
    }
    __syncthreads();

    // ---- main loop ----
    for (int kt = 0; kt < KT; kt++) {
        const int buf = kt & 1;
        const bool has_next = (kt + 1) < KT;

        // prefetch next tile into registers (LDG issued before compute)
        float4 av_n;
        float4 bv_n[4];
        if (has_next) {
            const int kb = (kt + 1) * BK;
            const float* Aptr;
            int koff;
            if (kb < KIN) { Aptr = x;  koff = kb; }
            else          { Aptr = hx; koff = kb - KIN; }
            av_n = *(const float4*)(Aptr + (size_t)(bm + arow) * KIN + koff + acol);
            if (kb < KIN) {
#pragma unroll
                for (int gg = 0; gg < 4; gg++)
                    bv_n[gg] = *(const float4*)(Wx[gg] + (size_t)(koff + brow) * NDIM + bn + bcol);
            } else {
#pragma unroll
                for (int gg = 0; gg < 4; gg++)
                    bv_n[gg] = *(const float4*)(Wh[gg] + (size_t)(koff + brow) * NDIM + bn + bcol);
            }
        }

        // compute on current stage
        {
            const unsigned* As = smem + buf * STAGE_SIZE;
            const unsigned* Bs = smem + buf * STAGE_SIZE + AS_SIZE + g * BK * BS_STRIDE;
#pragma unroll
            for (int ks = 0; ks < 2; ks++) {
                const int k0 = ks * 8;
                unsigned a[2][4];
#pragma unroll
                for (int t = 0; t < 2; t++) {
                    const int rb = mh * 32 + t * 16;
                    a[t][0] = As[(rb + r) * AS_STRIDE + k0 + c];
                    a[t][1] = As[(rb + r + 8) * AS_STRIDE + k0 + c];
                    a[t][2] = As[(rb + r) * AS_STRIDE + k0 + c + 4];
                    a[t][3] = As[(rb + r + 8) * AS_STRIDE + k0 + c + 4];
                }
#pragma unroll
                for (int j = 0; j < 8; j++) {
                    const unsigned b0 = Bs[(k0 + c) * BS_STRIDE + j * 8 + r];
                    const unsigned b1 = Bs[(k0 + c + 4) * BS_STRIDE + j * 8 + r];
                    mma_tf32(acc[0][j], a[0][0], a[0][1], a[0][2], a[0][3], b0, b1);
                    mma_tf32(acc[1][j], a[1][0], a[1][1], a[1][2], a[1][3], b0, b1);
                }
            }
        }

        // stage next tile into the other buffer
        if (has_next) {
            unsigned* As = smem + (buf ^ 1) * STAGE_SIZE;
            uint4 ua;
            ua.x = f2tf32(av_n.x); ua.y = f2tf32(av_n.y); ua.z = f2tf32(av_n.z); ua.w = f2tf32(av_n.w);
            *(uint4*)(As + arow * AS_STRIDE + acol) = ua;
            unsigned* Bs = smem + (buf ^ 1) * STAGE_SIZE + AS_SIZE;
#pragma unroll
            for (int gg = 0; gg < 4; gg++) {
                uint4 ub;
                ub.x = f2tf32(bv_n[gg].x); ub.y = f2tf32(bv_n[gg].y);
                ub.z = f2tf32(bv_n[gg].z); ub.w = f2tf32(bv_n[gg].w);
                *(uint4*)(Bs + gg * BK * BS_STRIDE + brow * BS_STRIDE + bcol) = ub;
            }
        }
        __syncthreads();
    }

    // ---- epilogue: combine gates, apply activations, write hy/cy ----
    float* eps = (float*)smem;                 // [4][32][64], 32 KB, reuses mainloop smem
    const size_t outCY = (size_t)MDIM * NDIM;  // d_out = [hy ; cy]

#pragma unroll
    for (int ph = 0; ph < 2; ph++) {
        __syncthreads();
        if (mh == ph) {
#pragma unroll
            for (int t = 0; t < 2; t++) {
#pragma unroll
                for (int j = 0; j < 8; j++) {
                    const int row0 = t * 16 + r;
                    const int col0 = j * 8 + c * 2;
                    eps[(g * 32 + row0) * 64 + col0]         = acc[t][j][0];
                    eps[(g * 32 + row0) * 64 + col0 + 1]     = acc[t][j][1];
                    eps[(g * 32 + row0 + 8) * 64 + col0]     = acc[t][j][2];
                    eps[(g * 32 + row0 + 8) * 64 + col0 + 1] = acc[t][j][3];
                }
            }
        }
        __syncthreads();

        for (int idx = tid; idx < 32 * 64; idx += THREADS) {
            const int ml = idx >> 6;
            const int nl = idx & 63;
            const int gm = bm + ph * 32 + ml;
            const int gn = bn + nl;

            const float zi = eps[(0 * 32 + ml) * 64 + nl] + bi[gn];
            const float zf = eps[(1 * 32 + ml) * 64 + nl] + bf_[gn];
            const float zc = eps[(2 * 32 + ml) * 64 + nl] + bc[gn];
            const float zo = eps[(3 * 32 + ml) * 64 + nl] + bo[gn];

            const float ig = 1.0f / (1.0f + expf(-zi));
            const float fg = 1.0f / (1.0f + expf(-zf));
            const float og = 1.0f / (1.0f + expf(-zo));
            const float ct = tanhf(zc);

            const float cprev = cx[(size_t)gm * NDIM + gn];
            const float cy = fg * cprev + ig * ct;
            const float hy = og * tanhf(cy);

            out[(size_t)gm * NDIM + gn] = hy;
            out[outCY + (size_t)gm * NDIM + gn] = cy;
        }
    }
}

extern "C" void kernel_launch(void* const* d_in, const int* in_sizes, int n_in,
                              void* d_out, int out_size) {
    (void)in_sizes; (void)n_in; (void)out_size;
    dim3 grid(NDIM / BN, MDIM / BM);   // 32 x 64 = 2048 CTAs
    lstm_fused_tf32_kernel<<<grid, THREADS, SMEM_WORDS * sizeof(unsigned)>>>(
        (const float*)d_in[0],  (const float*)d_in[1],  (const float*)d_in[2],
        (const float*)d_in[3],  (const float*)d_in[4],  (const float*)d_in[5],
        (const float*)d_in[6],  (const float*)d_in[7],  (const float*)d_in[8],
        (const float*)d_in[9],  (const float*)d_in[10], (const float*)d_in[11],
        (const float*)d_in[12], (const float*)d_in[13], (const float*)d_in[14],
        (float*)d_out);
}

// round 3
// speedup vs baseline: 1.4943x; 1.4943x over previous
#include <cuda_runtime.h>
#include <math.h>

// LSTM cell fused kernel, TF32 mma.sync path.
// M=BATCH=4096, N=HIDDEN=2048, K = 2048 (x) + 2048 (h) = 4096 effective.
// Computes all 4 gate pre-activations per output tile in one CTA, then the
// elementwise LSTM update, writing [hy ; cy] to d_out.

#define MDIM 4096
#define NDIM 2048
#define KIN  2048
#define BM 64
#define BN 64
#define BK 16
#define KT 256            // 4096 / 16
#define THREADS 256

#define AS_STRIDE 20      // 64 rows x 20 (16 + 4 pad) -> conflict-free frag loads
#define BS_STRIDE 72      // 16 rows x 72 (64 + 8 pad) -> conflict-free frag loads
#define AS_SIZE   (BM * AS_STRIDE)        // 1280 words
#define BS_SIZE   (4 * BK * BS_STRIDE)    // 4608 words
#define STAGE_SIZE (AS_SIZE + BS_SIZE)    // 5888 words
#define SMEM_WORDS (2 * STAGE_SIZE)       // 11776 words = 47104 B (< 48KB)

__device__ __forceinline__ unsigned f2tf32(float f) {
    unsigned r;
    asm("cvt.rna.tf32.f32 %0, %1;" : "=r"(r) : "f"(f));
    return r;
}

__device__ __forceinline__ void mma_tf32(float c[4],
                                         unsigned a0, unsigned a1, unsigned a2, unsigned a3,
                                         unsigned b0, unsigned b1) {
    asm volatile(
        "mma.sync.aligned.m16n8k8.row.col.f32.tf32.tf32.f32 "
        "{%0,%1,%2,%3}, {%4,%5,%6,%7}, {%8,%9}, {%0,%1,%2,%3};\n"
        : "+f"(c[0]), "+f"(c[1]), "+f"(c[2]), "+f"(c[3])
        : "r"(a0), "r"(a1), "r"(a2), "r"(a3), "r"(b0), "r"(b1));
}

__global__ __launch_bounds__(THREADS)
void lstm_fused_tf32_kernel(
    const float* __restrict__ x,   const float* __restrict__ hx,  const float* __restrict__ cx,
    const float* __restrict__ Wxi, const float* __restrict__ Whi, const float* __restrict__ bi,
    const float* __restrict__ Wxf, const float* __restrict__ Whf, const float* __restrict__ bf_,
    const float* __restrict__ Wxc, const float* __restrict__ Whc, const float* __restrict__ bc,
    const float* __restrict__ Wxo, const float* __restrict__ Who, const float* __restrict__ bo,
    float* __restrict__ out)
{
    extern __shared__ unsigned smem[];

    const int tid  = threadIdx.x;
    const int lane = tid & 31;
    const int wid  = tid >> 5;
    const int g    = wid & 3;   // gate: 0=i 1=f 2=c 3=o
    const int mh   = wid >> 2;  // m-half: 0 or 1 (rows 0-31 / 32-63 of tile)

    const int bm = blockIdx.y * BM;
    const int bn = blockIdx.x * BN;

    const float* const Wx[4] = {Wxi, Wxf, Wxc, Wxo};
    const float* const Wh[4] = {Whi, Whf, Whc, Who};

    // accumulators: [m-subtile (16 rows)][n-subtile (8 cols)][frag]
    float acc[2][8][4];
#pragma unroll
    for (int t = 0; t < 2; t++)
#pragma unroll
        for (int j = 0; j < 8; j++)
#pragma unroll
            for (int q = 0; q < 4; q++) acc[t][j][q] = 0.0f;

    // global load indexing
    const int arow = tid >> 2;          // 0..63
    const int acol = (tid & 3) * 4;     // 0,4,8,12
    const int brow = tid >> 4;          // 0..15
    const int bcol = (tid & 15) * 4;    // 0..60

    const int r = lane >> 2;            // 0..7
    const int c = lane & 3;             // 0..3

    // ---- prologue: load tile 0 into stage 0 ----
    {
        const float4 av = *(const float4*)(x + (size_t)(bm + arow) * KIN + acol);
        unsigned* As = smem;
        uint4 ua;
        ua.x = f2tf32(av.x); ua.y = f2tf32(av.y); ua.z = f2tf32(av.z); ua.w = f2tf32(av.w);
        *(uint4*)(As + arow * AS_STRIDE + acol) = ua;

        unsigned* Bs = smem + AS_SIZE;
#pragma unroll
        for (int gg = 0; gg < 4; gg++) {
            const float4 bv = *(const float4*)(Wx[gg] + (size_t)brow * NDIM + bn + bcol);
            uint4 ub;
            ub.x = f2tf32(bv.x); ub.y = f2tf32(bv.y); ub.z = f2tf32(bv.z); ub.w = f2tf32(bv.w);
            *(uint4*)(Bs + gg * BK * BS_STRIDE + brow * BS_STRIDE + bcol) = ub;
        }
    }
    __syncthreads();

    // ---- main loop ----
    for (int kt = 0; kt < KT; kt++) {
        const int buf = kt & 1;
        const bool has_next = (kt + 1) < KT;

        // prefetch next tile into registers (LDG issued before compute)
        float4 av_n;
        float4 bv_n[4];
        if (has_next) {
            const int kb = (kt + 1) * BK;
            const float* Aptr;
            int koff;
            if (kb < KIN) { Aptr = x;  koff = kb; }
            else          { Aptr = hx; koff = kb - KIN; }
            av_n = *(const float4*)(Aptr + (size_t)(bm + arow) * KIN + koff + acol);
            if (kb < KIN) {
#pragma unroll
                for (int gg = 0; gg < 4; gg++)
                    bv_n[gg] = *(const float4*)(Wx[gg] + (size_t)(koff + brow) * NDIM + bn + bcol);
            } else {
#pragma unroll
                for (int gg = 0; gg < 4; gg++)
                    bv_n[gg] = *(const float4*)(Wh[gg] + (size_t)(koff + brow) * NDIM + bn + bcol);
            }
        }

        // compute on current stage
        {
            const unsigned* As = smem + buf * STAGE_SIZE;
            const unsigned* Bs = smem + buf * STAGE_SIZE + AS_SIZE + g * BK * BS_STRIDE;
#pragma unroll
            for (int ks = 0; ks < 2; ks++) {
                const int k0 = ks * 8;
                unsigned a[2][4];
#pragma unroll
                for (int t = 0; t < 2; t++) {
                    const int rb = mh * 32 + t * 16;
                    a[t][0] = As[(rb + r) * AS_STRIDE + k0 + c];
                    a[t][1] = As[(rb + r + 8) * AS_STRIDE + k0 + c];
                    a[t][2] = As[(rb + r) * AS_STRIDE + k0 + c + 4];
                    a[t][3] = As[(rb + r + 8) * AS_STRIDE + k0 + c + 4];
                }
#pragma unroll
                for (int j = 0; j < 8; j++) {
                    const unsigned b0 = Bs[(k0 + c) * BS_STRIDE + j * 8 + r];
                    const unsigned b1 = Bs[(k0 + c + 4) * BS_STRIDE + j * 8 + r];
                    mma_tf32(acc[0][j], a[0][0], a[0][1], a[0][2], a[0][3], b0, b1);
                    mma_tf32(acc[1][j], a[1][0], a[1][1], a[1][2], a[1][3], b0, b1);
                }
            }
        }

        // stage next tile into the other buffer
        if (has_next) {
            unsigned* As = smem + (buf ^ 1) * STAGE_SIZE;
            uint4 ua;
            ua.x = f2tf32(av_n.x); ua.y = f2tf32(av_n.y); ua.z = f2tf32(av_n.z); ua.w = f2tf32(av_n.w);
            *(uint4*)(As + arow * AS_STRIDE + acol) = ua;
            unsigned* Bs = smem + (buf ^ 1) * STAGE_SIZE + AS_SIZE;
#pragma unroll
            for (int gg = 0; gg < 4; gg++) {
                uint4 ub;
                ub.x = f2tf32(bv_n[gg].x); ub.y = f2tf32(bv_n[gg].y);
                ub.z = f2tf32(bv_n[gg].z); ub.w = f2tf32(bv_n[gg].w);
                *(uint4*)(Bs + gg * BK * BS_STRIDE + brow * BS_STRIDE + bcol) = ub;
            }
        }
        __syncthreads();
    }

    // ---- epilogue: combine gates, apply activations, write hy/cy ----
    float* eps = (float*)smem;                 // [4][32][64], 32 KB, reuses mainloop smem
    const size_t outCY = (size_t)MDIM * NDIM;  // d_out = [hy ; cy]

#pragma unroll
    for (int ph = 0; ph < 2; ph++) {
        __syncthreads();
        if (mh == ph) {
#pragma unroll
            for (int t = 0; t < 2; t++) {
#pragma unroll
                for (int j = 0; j < 8; j++) {
                    const int row0 = t * 16 + r;
                    const int col0 = j * 8 + c * 2;
                    eps[(g * 32 + row0) * 64 + col0]         = acc[t][j][0];
                    eps[(g * 32 + row0) * 64 + col0 + 1]     = acc[t][j][1];
                    eps[(g * 32 + row0 + 8) * 64 + col0]     = acc[t][j][2];
                    eps[(g * 32 + row0 + 8) * 64 + col0 + 1] = acc[t][j][3];
                }
            }
        }
        __syncthreads();

        for (int idx = tid; idx < 32 * 64; idx += THREADS) {
            const int ml = idx >> 6;
            const int nl = idx & 63;
            const int gm = bm + ph * 32 + ml;
            const int gn = bn + nl;

            const float zi = eps[(0 * 32 + ml) * 64 + nl] + bi[gn];
            const float zf = eps[(1 * 32 + ml) * 64 + nl] + bf_[gn];
            const float zc = eps[(2 * 32 + ml) * 64 + nl] + bc[gn];
            const float zo = eps[(3 * 32 + ml) * 64 + nl] + bo[gn];

            const float ig = 1.0f / (1.0f + expf(-zi));
            const float fg = 1.0f / (1.0f + expf(-zf));
            const float og = 1.0f / (1.0f + expf(-zo));
            const float ct = tanhf(zc);

            const float cprev = cx[(size_t)gm * NDIM + gn];
            const float cy = fg * cprev + ig * ct;
            const float hy = og * tanhf(cy);

            out[(size_t)gm * NDIM + gn] = hy;
            out[outCY + (size_t)gm * NDIM + gn] = cy;
        }
    }
}

extern "C" void kernel_launch(void* const* d_in, const int* in_sizes, int n_in,
                              void* d_out, int out_size) {
    (void)in_sizes; (void)n_in; (void)out_size;
    dim3 grid(NDIM / BN, MDIM / BM);   // 32 x 64 = 2048 CTAs
    lstm_fused_tf32_kernel<<<grid, THREADS, SMEM_WORDS * sizeof(unsigned)>>>(
        (const float*)d_in[0],  (const float*)d_in[1],  (const float*)d_in[2],
        (const float*)d_in[3],  (const float*)d_in[4],  (const float*)d_in[5],
        (const float*)d_in[6],  (const float*)d_in[7],  (const float*)d_in[8],
        (const float*)d_in[9],  (const float*)d_in[10], (const float*)d_in[11],
        (const float*)d_in[12], (const float*)d_in[13], (const float*)d_in[14],
        (float*)d_out);
}

// round 6
// speedup vs baseline: 3.6476x; 2.4411x over previous
#include <cuda_runtime.h>
#include <cuda_fp16.h>
#include <math.h>
#include <stdint.h>

// ============================================================================
// LSTM cell, fp16 mma.sync.m16n8k16 path (sm_103 base target — no tcgen05).
//   prep_A: fp16-rn convert [x|h]        -> g_Ah  [m][k]   (K-major)
//   prep_W: transpose + fp16-rn weights  -> g_Wh  [g][n][k] (K-major)
//   main:   BM64 x BN64 tile, 8 warps = 4 gates x 2 m-halves, BK=64,
//           2-stage cp.async ring, ldmatrix.x4.b16 fragments,
//           fused sigmoid/tanh epilogue -> out = [hy ; cy]
// ============================================================================

#define MDIM 4096
#define NDIM 2048
#define KDIM 4096
#define BM 64
#define BN 64
#define BK 64                 // halves per k-stage = 128B rows
#define KT (KDIM / BK)        // 64
#define THREADS 256

#define A_STAGE_BYTES  (BM * 128)            // 8192
#define BG_STAGE_BYTES (BN * 128)            // 8192 per gate
#define STAGE_BYTES    (A_STAGE_BYTES + 4 * BG_STAGE_BYTES)   // 40960
#define SMEM_TOTAL     (2 * STAGE_BYTES)                      // 81920

#define SWZ(o) ((o) ^ (((o) >> 3) & 0x70))

__device__ uint4 g_Ah4[(size_t)MDIM * KDIM / 8];        // fp16 [m][k]
__device__ uint4 g_Wh4[(size_t)4 * NDIM * KDIM / 8];    // fp16 [g][n][k]

// ------------------------------ helpers ------------------------------------
__device__ __forceinline__ uint32_t smem_u32_of(const void* p) {
    uint32_t a;
    asm("{ .reg .u64 t; cvta.to.shared.u64 t, %1; cvt.u32.u64 %0, t; }" : "=r"(a) : "l"(p));
    return a;
}

#define CP_ASYNC16(dst, src) \
    asm volatile("cp.async.cg.shared.global [%0], [%1], 16;" :: "r"(dst), "l"(src) : "memory")
#define CP_COMMIT()  asm volatile("cp.async.commit_group;" ::: "memory")
#define CP_WAIT1()   asm volatile("cp.async.wait_group 1;" ::: "memory")

#define LDSM_X4(d, addr) \
    asm volatile("ldmatrix.sync.aligned.m8n8.x4.shared.b16 {%0,%1,%2,%3}, [%4];" \
        : "=r"((d)[0]), "=r"((d)[1]), "=r"((d)[2]), "=r"((d)[3]) : "r"(addr))

__device__ __forceinline__ void mma16816(float c[4], const uint32_t a[4],
                                         uint32_t b0, uint32_t b1) {
    asm volatile(
        "mma.sync.aligned.m16n8k16.row.col.f32.f16.f16.f32 "
        "{%0,%1,%2,%3}, {%4,%5,%6,%7}, {%8,%9}, {%0,%1,%2,%3};\n"
        : "+f"(c[0]), "+f"(c[1]), "+f"(c[2]), "+f"(c[3])
        : "r"(a[0]), "r"(a[1]), "r"(a[2]), "r"(a[3]), "r"(b0), "r"(b1));
}

// ------------------------------ pre-passes ---------------------------------
__global__ void prep_A(const float* __restrict__ x, const float* __restrict__ h) {
    const size_t idx = (size_t)blockIdx.x * blockDim.x + threadIdx.x;  // 2^21 threads
    const int m = (int)(idx >> 9);
    const int k = (int)(idx & 511) * 8;
    const float* s = (k < 2048) ? x + (size_t)m * 2048 + k
                                : h + (size_t)m * 2048 + (k - 2048);
    const float4 v0 = ((const float4*)s)[0];
    const float4 v1 = ((const float4*)s)[1];
    __half2 p0 = __floats2half2_rn(v0.x, v0.y);
    __half2 p1 = __floats2half2_rn(v0.z, v0.w);
    __half2 p2 = __floats2half2_rn(v1.x, v1.y);
    __half2 p3 = __floats2half2_rn(v1.z, v1.w);
    uint4 o;
    o.x = *(uint32_t*)&p0; o.y = *(uint32_t*)&p1;
    o.z = *(uint32_t*)&p2; o.w = *(uint32_t*)&p3;
    g_Ah4[idx] = o;
}

__global__ void prep_W(const float* Wxi, const float* Whi, const float* Wxf, const float* Whf,
                       const float* Wxc, const float* Whc, const float* Wxo, const float* Who) {
    __shared__ float t[32][33];
    const float* Wx[4] = {Wxi, Wxf, Wxc, Wxo};
    const float* Wh[4] = {Whi, Whf, Whc, Who};
    const int g  = blockIdx.z;
    const int k0 = blockIdx.x * 32, n0 = blockIdx.y * 32;
    const float* src = (k0 < 2048) ? Wx[g] : Wh[g];
    const int kk = k0 & 2047;
    const int tx = threadIdx.x, ty = threadIdx.y;
    __half* gW = (__half*)g_Wh4;
#pragma unroll
    for (int j = 0; j < 4; j++)
        t[ty + 8 * j][tx] = src[(size_t)(kk + ty + 8 * j) * NDIM + n0 + tx];
    __syncthreads();
#pragma unroll
    for (int j = 0; j < 4; j++)
        gW[((size_t)g * NDIM + n0 + ty + 8 * j) * KDIM + k0 + tx] =
            __float2half_rn(t[tx][ty + 8 * j]);
}

// ------------------------------ main kernel --------------------------------
__device__ __forceinline__ void load_stage(uint32_t st, int kb, int tid, int bm, int bn) {
    const __half* gA = (const __half*)g_Ah4;
    const __half* gW = (const __half*)g_Wh4;
#pragma unroll
    for (int i = 0; i < 10; i++) {
        const int ch = tid + i * 256;                 // 0..2559
        if (ch < 512) {                               // A: 64 rows x 8 chunks
            const int row = ch >> 3, c16 = ch & 7;
            const __half* src = gA + (size_t)(bm + row) * KDIM + kb + c16 * 8;
            CP_ASYNC16(st + SWZ(row * 128 + c16 * 16), src);
        } else {                                      // B: 4 gates x 64 rows x 8
            const int b = ch - 512;
            const int gg = b >> 9, bb = b & 511;
            const int row = bb >> 3, c16 = bb & 7;
            const __half* src = gW + ((size_t)gg * NDIM + bn + row) * KDIM + kb + c16 * 8;
            CP_ASYNC16(st + A_STAGE_BYTES + gg * BG_STAGE_BYTES + SWZ(row * 128 + c16 * 16), src);
        }
    }
    CP_COMMIT();
}

__global__ __launch_bounds__(THREADS, 2)
void lstm_fp16_kernel(const float* __restrict__ cx,
                      const float* __restrict__ bi, const float* __restrict__ bf_,
                      const float* __restrict__ bc, const float* __restrict__ bo,
                      float* __restrict__ out) {
    extern __shared__ char smem[];
    const uint32_t sbase = smem_u32_of(smem);

    const int tid  = threadIdx.x;
    const int lane = tid & 31;
    const int wid  = tid >> 5;
    const int g    = wid & 3;    // gate
    const int mh   = wid >> 2;   // m-half (rows 0-31 / 32-63)

    const int bn = blockIdx.x * BN;
    const int bm = blockIdx.y * BM;

    float acc[2][8][4];
#pragma unroll
    for (int t = 0; t < 2; t++)
#pragma unroll
        for (int j = 0; j < 8; j++)
#pragma unroll
            for (int q = 0; q < 4; q++) acc[t][j][q] = 0.0f;

    // per-lane ldmatrix geometry
    const int j8    = lane & 7;          // row within 8-row matrix
    const int mm    = lane >> 3;         // matrix index in x4
    const int mlo   = (mm & 1) * 8;
    const int khalf = (mm >> 1) * 16;    // byte offset selecting k0-7 / k8-15
    const int S     = j8 << 4;           // swizzle term (row & 7) << 4
    const int rowA  = mh * 32 + mlo + j8;
    const int rowB  = mlo + j8;

    // prologue: fill both stages
    load_stage(sbase, 0, tid, bm, bn);
    load_stage(sbase + STAGE_BYTES, BK, tid, bm, bn);

    for (int kt = 0; kt < KT; kt++) {
        CP_WAIT1();
        __syncthreads();

        const uint32_t stA = sbase + (kt & 1) * STAGE_BYTES;
        const uint32_t stB = stA + A_STAGE_BYTES + g * BG_STAGE_BYTES;

#pragma unroll
        for (int ks = 0; ks < 4; ks++) {
            const int KX = (ks * 32 + khalf) ^ S;
            uint32_t a[2][4], b[4][4];
            LDSM_X4(a[0], stA + rowA * 128 + KX);
            LDSM_X4(a[1], stA + (rowA + 16) * 128 + KX);
#pragma unroll
            for (int p = 0; p < 4; p++)
                LDSM_X4(b[p], stB + (rowB + p * 16) * 128 + KX);
#pragma unroll
            for (int t = 0; t < 2; t++)
#pragma unroll
                for (int j = 0; j < 8; j++) {
                    const int p = j >> 1, o = j & 1;
                    mma16816(acc[t][j], a[t], b[p][o], b[p][o + 2]);
                }
        }
        __syncthreads();

        if (kt + 2 < KT) load_stage(sbase + (kt & 1) * STAGE_BYTES, (kt + 2) * BK, tid, bm, bn);
        else             CP_COMMIT();   // keep 2-outstanding invariant for WAIT1
    }

    // ---- epilogue: combine gates, activations, write hy/cy ----
    float* eps = (float*)smem;                 // [4][32][64] = 32 KB
    const size_t outCY = (size_t)MDIM * NDIM;
    const int r = lane >> 2;
    const int c = lane & 3;

#pragma unroll
    for (int ph = 0; ph < 2; ph++) {
        __syncthreads();
        if (mh == ph) {
#pragma unroll
            for (int t = 0; t < 2; t++) {
#pragma unroll
                for (int j = 0; j < 8; j++) {
                    const int row0 = t * 16 + r;
                    const int col0 = j * 8 + c * 2;
                    eps[(g * 32 + row0) * 64 + col0]         = acc[t][j][0];
                    eps[(g * 32 + row0) * 64 + col0 + 1]     = acc[t][j][1];
                    eps[(g * 32 + row0 + 8) * 64 + col0]     = acc[t][j][2];
                    eps[(g * 32 + row0 + 8) * 64 + col0 + 1] = acc[t][j][3];
                }
            }
        }
        __syncthreads();

        for (int idx = tid; idx < 32 * 64; idx += THREADS) {
            const int ml = idx >> 6;
            const int nl = idx & 63;
            const int gm = bm + ph * 32 + ml;
            const int gn = bn + nl;

            const float zi = eps[(0 * 32 + ml) * 64 + nl] + bi[gn];
            const float zf = eps[(1 * 32 + ml) * 64 + nl] + bf_[gn];
            const float zc = eps[(2 * 32 + ml) * 64 + nl] + bc[gn];
            const float zo = eps[(3 * 32 + ml) * 64 + nl] + bo[gn];

            const float ig = 1.0f / (1.0f + expf(-zi));
            const float fg = 1.0f / (1.0f + expf(-zf));
            const float og = 1.0f / (1.0f + expf(-zo));
            const float ct = tanhf(zc);

            const float cprev = cx[(size_t)gm * NDIM + gn];
            const float cy = fg * cprev + ig * ct;
            const float hy = og * tanhf(cy);

            out[(size_t)gm * NDIM + gn] = hy;
            out[outCY + (size_t)gm * NDIM + gn] = cy;
        }
    }
}

// ------------------------------- launch ------------------------------------
extern "C" void kernel_launch(void* const* d_in, const int* in_sizes, int n_in,
                              void* d_out, int out_size) {
    (void)in_sizes; (void)n_in; (void)out_size;
    cudaFuncSetAttribute(lstm_fp16_kernel,
                         cudaFuncAttributeMaxDynamicSharedMemorySize, SMEM_TOTAL);

    prep_A<<<8192, 256>>>((const float*)d_in[0], (const float*)d_in[1]);
    prep_W<<<dim3(KDIM / 32, NDIM / 32, 4), dim3(32, 8)>>>(
        (const float*)d_in[3],  (const float*)d_in[4],    // W_xi, W_hi
        (const float*)d_in[6],  (const float*)d_in[7],    // W_xf, W_hf
        (const float*)d_in[9],  (const float*)d_in[10],   // W_xc, W_hc
        (const float*)d_in[12], (const float*)d_in[13]);  // W_xo, W_ho

    dim3 grid(NDIM / BN, MDIM / BM);   // 32 x 64 = 2048 CTAs
    lstm_fp16_kernel<<<grid, THREADS, SMEM_TOTAL>>>(
        (const float*)d_in[2],                           // c_x
        (const float*)d_in[5],  (const float*)d_in[8],   // b_i, b_f
        (const float*)d_in[11], (const float*)d_in[14],  // b_c, b_o
        (float*)d_out);
}